// round 4
// baseline (speedup 1.0000x reference)
#include <cuda_runtime.h>

#define H 64
#define NMAX 50000
#define EMAX 800000

// ---- static scratch (no allocations allowed) ----
__device__ float g_h[NMAX * H];     // encoder output
__device__ float g_hw[NMAX * H];    // h @ W[l]
__device__ float g_aggA[NMAX * H];  // ping
__device__ float g_aggB[NMAX * H];  // pong
__device__ float g_dinv[NMAX];
__device__ int   g_cnt[NMAX];       // in-degree (excl self-loop)
__device__ int   g_off[NMAX + 1];   // CSR row offsets (by dst)
__device__ int   g_cur[NMAX];       // fill cursors
__device__ int2  g_csr[EMAX];       // (src, bitcast(norm)) per edge

__device__ __forceinline__ float* buf_ptr(int s) {
    return (s == 0) ? g_h : (s == 1) ? g_aggA : g_aggB;
}

// ---------------- encoder: h = relu(x @ W_enc + b_enc); also clears g_cnt ----
__global__ void __launch_bounds__(256) encoder_k(
    const float* __restrict__ x, const float* __restrict__ W,
    const float* __restrict__ b, int N)
{
    __shared__ float sW[5 * 64];
    __shared__ float sb[64];
    int t = threadIdx.x;
    for (int i = t; i < 320; i += 256) sW[i] = W[i];
    if (t < 64) sb[t] = b[t];
    __syncthreads();

    int gid = blockIdx.x * 256 + t;
    if (gid < N) g_cnt[gid] = 0;          // fused histogram clear
    if (gid >= N * 16) return;
    int i = gid >> 4;
    int c = (gid & 15) * 4;

    float xv[5];
#pragma unroll
    for (int f = 0; f < 5; f++) xv[f] = x[i * 5 + f];

    float a0 = sb[c], a1 = sb[c + 1], a2 = sb[c + 2], a3 = sb[c + 3];
#pragma unroll
    for (int f = 0; f < 5; f++) {
        const float* wr = &sW[f * 64 + c];
        a0 += xv[f] * wr[0];
        a1 += xv[f] * wr[1];
        a2 += xv[f] * wr[2];
        a3 += xv[f] * wr[3];
    }
    float4 o;
    o.x = fmaxf(a0, 0.f); o.y = fmaxf(a1, 0.f);
    o.z = fmaxf(a2, 0.f); o.w = fmaxf(a3, 0.f);
    *(float4*)&g_h[i * 64 + c] = o;
}

// ---------------- degree histogram ----------------
__global__ void deg_count_k(const int* __restrict__ dst, int E) {
    int e = blockIdx.x * blockDim.x + threadIdx.x;
    if (e < E) atomicAdd(&g_cnt[dst[e]], 1);
}

// ---------------- one-pass coarsened scan + dinv + cursor init ----------------
__global__ void __launch_bounds__(1024) scan_dinv_k(int N) {
    __shared__ int sWarp[32];
    int tid = threadIdx.x;
    int lane = tid & 31, w = tid >> 5;
    int C = (N + 1023) >> 10;    // elements per thread
    int base = tid * C;

    int s = 0;
    for (int c = 0; c < C; c++) {
        int i = base + c;
        if (i < N) s += g_cnt[i];
    }
    // inclusive warp scan
    int x = s;
#pragma unroll
    for (int o = 1; o < 32; o <<= 1) {
        int y = __shfl_up_sync(0xffffffffu, x, o);
        if (lane >= o) x += y;
    }
    if (lane == 31) sWarp[w] = x;
    __syncthreads();
    if (w == 0) {
        int v = sWarp[lane];
#pragma unroll
        for (int o = 1; o < 32; o <<= 1) {
            int y = __shfl_up_sync(0xffffffffu, v, o);
            if (lane >= o) v += y;
        }
        sWarp[lane] = v;
    }
    __syncthreads();
    int pref = x - s + ((w > 0) ? sWarp[w - 1] : 0);  // exclusive prefix
    if (tid == 0) g_off[N] = sWarp[31];

    for (int c = 0; c < C; c++) {
        int i = base + c;
        if (i < N) {
            int cnt = g_cnt[i];
            g_off[i] = pref;
            g_cur[i] = pref;
            g_dinv[i] = rsqrtf(1.0f + (float)cnt);
            pref += cnt;
        }
    }
}

// ---------------- CSR fill ----------------
__global__ void csr_fill_k(const int* __restrict__ src,
                           const int* __restrict__ dst, int E) {
    int e = blockIdx.x * blockDim.x + threadIdx.x;
    if (e >= E) return;
    int s = src[e];
    int c = dst[e];
    float w = g_dinv[s] * g_dinv[c];
    int pos = atomicAdd(&g_cur[c], 1);
    g_csr[pos] = make_int2(s, __float_as_int(w));
}

// ---------------- GEMM: hw = preop(in) @ W ----------------
__global__ void __launch_bounds__(256) gemm_k(
    int in_sel, const float* __restrict__ W,
    const float* __restrict__ preb, int hasPre, int N)
{
    __shared__ float sW[64 * 64];
    __shared__ float sIn[64 * 65];

    const float* __restrict__ in = buf_ptr(in_sel);

    int t = threadIdx.x;
    int i0 = blockIdx.x * 64;

    {
        const float4* Wv = (const float4*)W;
        float4* sWv = (float4*)sW;
#pragma unroll
        for (int r = 0; r < 4; r++) sWv[t + r * 256] = Wv[t + r * 256];
    }
#pragma unroll
    for (int r = 0; r < 4; r++) {
        int lin = t + r * 256;
        int n = lin >> 4;
        int c4 = (lin & 15) * 4;
        int i = i0 + n;
        float4 v = make_float4(0.f, 0.f, 0.f, 0.f);
        if (i < N) v = *(const float4*)&in[i * 64 + c4];
        if (hasPre) {
            v.x = fmaxf(v.x + preb[c4 + 0], 0.f);
            v.y = fmaxf(v.y + preb[c4 + 1], 0.f);
            v.z = fmaxf(v.z + preb[c4 + 2], 0.f);
            v.w = fmaxf(v.w + preb[c4 + 3], 0.f);
        }
        float* s = &sIn[n * 65 + c4];
        s[0] = v.x; s[1] = v.y; s[2] = v.z; s[3] = v.w;
    }
    __syncthreads();

    int n = t >> 2;
    int q = t & 3;
    int i = i0 + n;

    float acc[16];
#pragma unroll
    for (int j = 0; j < 16; j++) acc[j] = 0.f;

#pragma unroll 16
    for (int k = 0; k < 64; k++) {
        float hv = sIn[n * 65 + k];
        const float4* wp = (const float4*)&sW[k * 64 + q * 16];
        float4 w0 = wp[0], w1 = wp[1], w2 = wp[2], w3 = wp[3];
        acc[0]  += hv * w0.x; acc[1]  += hv * w0.y; acc[2]  += hv * w0.z; acc[3]  += hv * w0.w;
        acc[4]  += hv * w1.x; acc[5]  += hv * w1.y; acc[6]  += hv * w1.z; acc[7]  += hv * w1.w;
        acc[8]  += hv * w2.x; acc[9]  += hv * w2.y; acc[10] += hv * w2.z; acc[11] += hv * w2.w;
        acc[12] += hv * w3.x; acc[13] += hv * w3.y; acc[14] += hv * w3.z; acc[15] += hv * w3.w;
    }

    if (i < N) {
        float* hwp = &g_hw[i * 64 + q * 16];
#pragma unroll
        for (int r = 0; r < 4; r++) {
            float4 hv4 = make_float4(acc[r*4], acc[r*4+1], acc[r*4+2], acc[r*4+3]);
            *(float4*)&hwp[r * 4] = hv4;
        }
    }
}

// ---------------- pull aggregation core ----------------
__device__ __forceinline__ float4 agg_node(int i, int c4) {
    float dv = g_dinv[i];
    float dv2 = dv * dv;
    float4 hv = *(const float4*)&g_hw[i * 64 + c4];
    float4 acc = make_float4(hv.x * dv2, hv.y * dv2, hv.z * dv2, hv.w * dv2);

    int j = g_off[i];
    int end = g_off[i + 1];
    for (; j + 4 <= end; j += 4) {
        int2 e0 = g_csr[j + 0];
        int2 e1 = g_csr[j + 1];
        int2 e2 = g_csr[j + 2];
        int2 e3 = g_csr[j + 3];
        float4 v0 = *(const float4*)&g_hw[e0.x * 64 + c4];
        float4 v1 = *(const float4*)&g_hw[e1.x * 64 + c4];
        float4 v2 = *(const float4*)&g_hw[e2.x * 64 + c4];
        float4 v3 = *(const float4*)&g_hw[e3.x * 64 + c4];
        float w0 = __int_as_float(e0.y), w1 = __int_as_float(e1.y);
        float w2 = __int_as_float(e2.y), w3 = __int_as_float(e3.y);
        acc.x += v0.x * w0; acc.y += v0.y * w0; acc.z += v0.z * w0; acc.w += v0.w * w0;
        acc.x += v1.x * w1; acc.y += v1.y * w1; acc.z += v1.z * w1; acc.w += v1.w * w1;
        acc.x += v2.x * w2; acc.y += v2.y * w2; acc.z += v2.z * w2; acc.w += v2.w * w2;
        acc.x += v3.x * w3; acc.y += v3.y * w3; acc.z += v3.z * w3; acc.w += v3.w * w3;
    }
    for (; j < end; j++) {
        int2 e = g_csr[j];
        float4 v = *(const float4*)&g_hw[e.x * 64 + c4];
        float w = __int_as_float(e.y);
        acc.x += v.x * w; acc.y += v.y * w; acc.z += v.z * w; acc.w += v.w * w;
    }
    return acc;
}

// 16 lanes per node, lane owns 4 cols
__global__ void __launch_bounds__(256) aggregate_k(int agg_sel, int N)
{
    int idx = blockIdx.x * 256 + threadIdx.x;
    int i = idx >> 4;
    if (i >= N) return;
    int c4 = (idx & 15) * 4;
    float4 acc = agg_node(i, c4);
    float* agg = buf_ptr(agg_sel);
    *(float4*)&agg[i * 64 + c4] = acc;
}

// ---------------- fused final aggregate + relu/bias + two MLP heads ----------------
// warp handles 2 nodes (16 lanes each); block = 8 warps = 16 nodes
__global__ void __launch_bounds__(256) agg_heads_k(
    const float* __restrict__ cb,
    const float* __restrict__ Wd1, const float* __restrict__ bd1,
    const float* __restrict__ Wd2, const float* __restrict__ bd2,
    const float* __restrict__ Wi1, const float* __restrict__ bi1,
    const float* __restrict__ Wi2, const float* __restrict__ bi2,
    float* __restrict__ out, int N)
{
    __shared__ float sWd1[64 * 32];
    __shared__ float sWi1[64 * 32];
    __shared__ float sWd2[32], sWi2[32], sbd1[32], sbi1[32], scb[64];
    __shared__ float sh[8][2][64];

    int t = threadIdx.x;
    {
        const float4* wd = (const float4*)Wd1;
        const float4* wi = (const float4*)Wi1;
        float4* swd = (float4*)sWd1;
        float4* swi = (float4*)sWi1;
        swd[t] = wd[t]; swd[t + 256] = wd[t + 256];
        swi[t] = wi[t]; swi[t + 256] = wi[t + 256];
    }
    if (t < 32) { sWd2[t] = Wd2[t]; sWi2[t] = Wi2[t]; sbd1[t] = bd1[t]; sbi1[t] = bi1[t]; }
    if (t < 64) scb[t] = cb[t];
    __syncthreads();

    int w = t >> 5, lane = t & 31;
    int nw = lane >> 4;            // node within warp (0/1)
    int c4 = (lane & 15) * 4;
    int i = blockIdx.x * 16 + w * 2 + nw;

    if (i < N) {
        float4 acc = agg_node(i, c4);
        float* s = &sh[w][nw][c4];
        s[0] = fmaxf(acc.x + scb[c4 + 0], 0.f);
        s[1] = fmaxf(acc.y + scb[c4 + 1], 0.f);
        s[2] = fmaxf(acc.z + scb[c4 + 2], 0.f);
        s[3] = fmaxf(acc.w + scb[c4 + 3], 0.f);
    } else {
        float* s = &sh[w][nw][c4];
        s[0] = s[1] = s[2] = s[3] = 0.f;
    }
    __syncwarp();

    int i0 = blockIdx.x * 16 + w * 2;
    if (i0 >= N) return;

    float ad0 = sbd1[lane], ai0 = sbi1[lane];
    float ad1 = sbd1[lane], ai1 = sbi1[lane];
#pragma unroll 16
    for (int k = 0; k < 64; k++) {
        float h0 = sh[w][0][k];
        float h1 = sh[w][1][k];
        float wd = sWd1[k * 32 + lane];
        float wi = sWi1[k * 32 + lane];
        ad0 += h0 * wd; ai0 += h0 * wi;
        ad1 += h1 * wd; ai1 += h1 * wi;
    }
    float vd0 = fmaxf(ad0, 0.f) * sWd2[lane];
    float vi0 = fmaxf(ai0, 0.f) * sWi2[lane];
    float vd1 = fmaxf(ad1, 0.f) * sWd2[lane];
    float vi1 = fmaxf(ai1, 0.f) * sWi2[lane];
#pragma unroll
    for (int o = 16; o > 0; o >>= 1) {
        vd0 += __shfl_xor_sync(0xffffffffu, vd0, o);
        vi0 += __shfl_xor_sync(0xffffffffu, vi0, o);
        vd1 += __shfl_xor_sync(0xffffffffu, vd1, o);
        vi1 += __shfl_xor_sync(0xffffffffu, vi1, o);
    }
    if (lane == 0) {
        out[i0]     = vd0 + bd2[0];
        out[N + i0] = vi0 + bi2[0];
        int i1 = i0 + 1;
        if (i1 < N) {
            out[i1]     = vd1 + bd2[0];
            out[N + i1] = vi1 + bi2[0];
        }
    }
}

// ---------------- launch ----------------
extern "C" void kernel_launch(void* const* d_in, const int* in_sizes, int n_in,
                              void* d_out, int out_size)
{
    const float* x      = (const float*)d_in[0];
    const int*   ei     = (const int*)d_in[1];     // int32 (JAX x64 off)
    const float* W_enc  = (const float*)d_in[2];
    const float* b_enc  = (const float*)d_in[3];
    const float* conv_W = (const float*)d_in[4];   // [3][64][64]
    const float* conv_b = (const float*)d_in[5];   // [3][64]
    const float* W_d1   = (const float*)d_in[6];
    const float* b_d1   = (const float*)d_in[7];
    const float* W_d2   = (const float*)d_in[8];
    const float* b_d2   = (const float*)d_in[9];
    const float* W_i1   = (const float*)d_in[10];
    const float* b_i1   = (const float*)d_in[11];
    const float* W_i2   = (const float*)d_in[12];
    const float* b_i2   = (const float*)d_in[13];
    float* out = (float*)d_out;

    int N = in_sizes[0] / 5;
    int E = in_sizes[1] / 2;
    const int* src = ei;       // edge_index[0] (source)
    const int* dst = ei + E;   // edge_index[1] (target)

    int nbE = (E + 255) / 256;
    int gemmB = (N + 63) / 64;
    int aggB  = (N * 16 + 255) / 256;

    // 0: encoder (+ g_cnt clear)
    encoder_k<<<(N * 16 + 255) / 256, 256>>>(x, W_enc, b_enc, N);
    // 1: degree histogram
    deg_count_k<<<nbE, 256>>>(dst, E);
    // 2: scan + dinv + cursors
    scan_dinv_k<<<1, 1024>>>(N);
    // 3: CSR fill
    csr_fill_k<<<nbE, 256>>>(src, dst, E);
    // 4: layer0 gemm
    gemm_k<<<gemmB, 256>>>(0, conv_W + 0 * 4096, nullptr, 0, N);
    // 5: layer0 aggregate (ncu -s 5 lands here)
    aggregate_k<<<aggB, 256>>>(1, N);
    // 6-7: layer1
    gemm_k<<<gemmB, 256>>>(1, conv_W + 1 * 4096, conv_b + 0 * 64, 1, N);
    aggregate_k<<<aggB, 256>>>(2, N);
    // 8: layer2 gemm
    gemm_k<<<gemmB, 256>>>(2, conv_W + 2 * 4096, conv_b + 1 * 64, 1, N);
    // 9: fused layer2 aggregate + heads
    agg_heads_k<<<(N + 15) / 16, 256>>>(conv_b + 2 * 64,
                                        W_d1, b_d1, W_d2, b_d2,
                                        W_i1, b_i1, W_i2, b_i2,
                                        out, N);
}

// round 5
// speedup vs baseline: 1.2096x; 1.2096x over previous
#include <cuda_runtime.h>

#define H 64
#define NMAX 50000
#define EMAX 800000

// ---- static scratch (no allocations allowed) ----
__device__ float g_h[NMAX * H];     // encoder output
__device__ float g_hw[NMAX * H];    // h @ W[l]
__device__ float g_aggA[NMAX * H];  // ping
__device__ float g_aggB[NMAX * H];  // pong
__device__ float g_dinv[NMAX];
__device__ int   g_cnt[NMAX];       // in-degree (excl self-loop)
__device__ int   g_off[NMAX + 1];   // CSR row offsets (by dst)
__device__ int   g_cur[NMAX];       // fill cursors
__device__ int   g_csr[EMAX];       // src per edge (CSR by dst)

__device__ __forceinline__ float* buf_ptr(int s) {
    return (s == 0) ? g_h : (s == 1) ? g_aggA : g_aggB;
}

// ---------------- encoder: h = relu(x @ W_enc + b_enc); also clears g_cnt ----
__global__ void __launch_bounds__(256) encoder_k(
    const float* __restrict__ x, const float* __restrict__ W,
    const float* __restrict__ b, int N)
{
    __shared__ float sW[5 * 64];
    __shared__ float sb[64];
    int t = threadIdx.x;
    for (int i = t; i < 320; i += 256) sW[i] = W[i];
    if (t < 64) sb[t] = b[t];
    __syncthreads();

    int gid = blockIdx.x * 256 + t;
    if (gid < N) g_cnt[gid] = 0;          // fused histogram clear
    if (gid >= N * 16) return;
    int i = gid >> 4;
    int c = (gid & 15) * 4;

    float xv[5];
#pragma unroll
    for (int f = 0; f < 5; f++) xv[f] = x[i * 5 + f];

    float a0 = sb[c], a1 = sb[c + 1], a2 = sb[c + 2], a3 = sb[c + 3];
#pragma unroll
    for (int f = 0; f < 5; f++) {
        const float* wr = &sW[f * 64 + c];
        a0 += xv[f] * wr[0];
        a1 += xv[f] * wr[1];
        a2 += xv[f] * wr[2];
        a3 += xv[f] * wr[3];
    }
    float4 o;
    o.x = fmaxf(a0, 0.f); o.y = fmaxf(a1, 0.f);
    o.z = fmaxf(a2, 0.f); o.w = fmaxf(a3, 0.f);
    *(float4*)&g_h[i * 64 + c] = o;
}

// ---------------- degree histogram ----------------
__global__ void deg_count_k(const int* __restrict__ dst, int E) {
    int e = blockIdx.x * blockDim.x + threadIdx.x;
    if (e < E) atomicAdd(&g_cnt[dst[e]], 1);
}

// ---------------- one-pass coarsened scan + dinv + cursor init ----------------
__global__ void __launch_bounds__(1024) scan_dinv_k(int N) {
    __shared__ int sWarp[32];
    int tid = threadIdx.x;
    int lane = tid & 31, w = tid >> 5;
    int C = (N + 1023) >> 10;
    int base = tid * C;

    int s = 0;
    for (int c = 0; c < C; c++) {
        int i = base + c;
        if (i < N) s += g_cnt[i];
    }
    int x = s;
#pragma unroll
    for (int o = 1; o < 32; o <<= 1) {
        int y = __shfl_up_sync(0xffffffffu, x, o);
        if (lane >= o) x += y;
    }
    if (lane == 31) sWarp[w] = x;
    __syncthreads();
    if (w == 0) {
        int v = sWarp[lane];
#pragma unroll
        for (int o = 1; o < 32; o <<= 1) {
            int y = __shfl_up_sync(0xffffffffu, v, o);
            if (lane >= o) v += y;
        }
        sWarp[lane] = v;
    }
    __syncthreads();
    int pref = x - s + ((w > 0) ? sWarp[w - 1] : 0);
    if (tid == 0) g_off[N] = sWarp[31];

    for (int c = 0; c < C; c++) {
        int i = base + c;
        if (i < N) {
            int cnt = g_cnt[i];
            g_off[i] = pref;
            g_cur[i] = pref;
            g_dinv[i] = rsqrtf(1.0f + (float)cnt);
            pref += cnt;
        }
    }
}

// ---------------- CSR fill (src only; norm recomputed at use) ----------------
__global__ void csr_fill_k(const int* __restrict__ src,
                           const int* __restrict__ dst, int E) {
    int e = blockIdx.x * blockDim.x + threadIdx.x;
    if (e >= E) return;
    int s = src[e];
    int c = dst[e];
    int pos = atomicAdd(&g_cur[c], 1);
    g_csr[pos] = s;
}

// ---------------- GEMM: hw = preop(in) @ W ----------------
// 128 threads, 64-node tile; thread = 2 nodes x 16 cols (32 accumulators)
__global__ void __launch_bounds__(128) gemm_k(
    int in_sel, const float* __restrict__ W,
    const float* __restrict__ preb, int hasPre, int N)
{
    __shared__ float sW[64 * 64];
    __shared__ float sIn[64 * 65];

    const float* __restrict__ in = buf_ptr(in_sel);

    int t = threadIdx.x;
    int i0 = blockIdx.x * 64;

    {
        const float4* Wv = (const float4*)W;
        float4* sWv = (float4*)sW;
#pragma unroll
        for (int r = 0; r < 8; r++) sWv[t + r * 128] = Wv[t + r * 128];
    }
#pragma unroll
    for (int r = 0; r < 8; r++) {
        int lin = t + r * 128;        // float4 unit 0..1023
        int n = lin >> 4;
        int c4 = (lin & 15) * 4;
        int i = i0 + n;
        float4 v = make_float4(0.f, 0.f, 0.f, 0.f);
        if (i < N) v = *(const float4*)&in[i * 64 + c4];
        if (hasPre) {
            v.x = fmaxf(v.x + preb[c4 + 0], 0.f);
            v.y = fmaxf(v.y + preb[c4 + 1], 0.f);
            v.z = fmaxf(v.z + preb[c4 + 2], 0.f);
            v.w = fmaxf(v.w + preb[c4 + 3], 0.f);
        }
        float* s = &sIn[n * 65 + c4];
        s[0] = v.x; s[1] = v.y; s[2] = v.z; s[3] = v.w;
    }
    __syncthreads();

    int n2 = t >> 2;        // node pair 0..31
    int q  = t & 3;         // col quarter
    int na = 2 * n2, nb = na + 1;

    float acc0[16], acc1[16];
#pragma unroll
    for (int j = 0; j < 16; j++) { acc0[j] = 0.f; acc1[j] = 0.f; }

#pragma unroll 8
    for (int k = 0; k < 64; k++) {
        float h0 = sIn[na * 65 + k];
        float h1 = sIn[nb * 65 + k];
        const float4* wp = (const float4*)&sW[k * 64 + q * 16];
        float4 w0 = wp[0], w1 = wp[1], w2 = wp[2], w3 = wp[3];
        acc0[0]  += h0 * w0.x; acc0[1]  += h0 * w0.y; acc0[2]  += h0 * w0.z; acc0[3]  += h0 * w0.w;
        acc0[4]  += h0 * w1.x; acc0[5]  += h0 * w1.y; acc0[6]  += h0 * w1.z; acc0[7]  += h0 * w1.w;
        acc0[8]  += h0 * w2.x; acc0[9]  += h0 * w2.y; acc0[10] += h0 * w2.z; acc0[11] += h0 * w2.w;
        acc0[12] += h0 * w3.x; acc0[13] += h0 * w3.y; acc0[14] += h0 * w3.z; acc0[15] += h0 * w3.w;
        acc1[0]  += h1 * w0.x; acc1[1]  += h1 * w0.y; acc1[2]  += h1 * w0.z; acc1[3]  += h1 * w0.w;
        acc1[4]  += h1 * w1.x; acc1[5]  += h1 * w1.y; acc1[6]  += h1 * w1.z; acc1[7]  += h1 * w1.w;
        acc1[8]  += h1 * w2.x; acc1[9]  += h1 * w2.y; acc1[10] += h1 * w2.z; acc1[11] += h1 * w2.w;
        acc1[12] += h1 * w3.x; acc1[13] += h1 * w3.y; acc1[14] += h1 * w3.z; acc1[15] += h1 * w3.w;
    }

    int ia = i0 + na, ib = i0 + nb;
    if (ia < N) {
        float* p = &g_hw[ia * 64 + q * 16];
#pragma unroll
        for (int r = 0; r < 4; r++)
            *(float4*)&p[r * 4] = make_float4(acc0[r*4], acc0[r*4+1], acc0[r*4+2], acc0[r*4+3]);
    }
    if (ib < N) {
        float* p = &g_hw[ib * 64 + q * 16];
#pragma unroll
        for (int r = 0; r < 4; r++)
            *(float4*)&p[r * 4] = make_float4(acc1[r*4], acc1[r*4+1], acc1[r*4+2], acc1[r*4+3]);
    }
}

// ---------------- pull aggregation (no atomics), MLP-8 ----------------
__global__ void __launch_bounds__(256) aggregate_k(int agg_sel, int N)
{
    int idx = blockIdx.x * 256 + threadIdx.x;
    int i = idx >> 4;
    if (i >= N) return;
    int c4 = (idx & 15) * 4;

    float dv = g_dinv[i];
    float4 hv = *(const float4*)&g_hw[i * 64 + c4];
    float4 acc = make_float4(hv.x * dv, hv.y * dv, hv.z * dv, hv.w * dv);
    // acc currently = hw*dinv; self-loop term is hw*dinv^2; handle by tracking
    // everything in units of (1/dv):  agg = dv * ( hw*dv + sum_e hw[s]*dinv[s] )
    int j = g_off[i];
    int end = g_off[i + 1];

    while (j + 8 <= end) {
        int s[8];
#pragma unroll
        for (int g = 0; g < 8; g++) s[g] = g_csr[j + g];
        float w[8];
#pragma unroll
        for (int g = 0; g < 8; g++) w[g] = g_dinv[s[g]];
        float4 v[8];
#pragma unroll
        for (int g = 0; g < 8; g++) v[g] = __ldcg((const float4*)&g_hw[s[g] * 64 + c4]);
#pragma unroll
        for (int g = 0; g < 8; g++) {
            acc.x += v[g].x * w[g]; acc.y += v[g].y * w[g];
            acc.z += v[g].z * w[g]; acc.w += v[g].w * w[g];
        }
        j += 8;
    }
    while (j + 2 <= end) {
        int s0 = g_csr[j], s1 = g_csr[j + 1];
        float w0 = g_dinv[s0], w1 = g_dinv[s1];
        float4 v0 = __ldcg((const float4*)&g_hw[s0 * 64 + c4]);
        float4 v1 = __ldcg((const float4*)&g_hw[s1 * 64 + c4]);
        acc.x += v0.x * w0 + v1.x * w1; acc.y += v0.y * w0 + v1.y * w1;
        acc.z += v0.z * w0 + v1.z * w1; acc.w += v0.w * w0 + v1.w * w1;
        j += 2;
    }
    if (j < end) {
        int s0 = g_csr[j];
        float w0 = g_dinv[s0];
        float4 v0 = __ldcg((const float4*)&g_hw[s0 * 64 + c4]);
        acc.x += v0.x * w0; acc.y += v0.y * w0;
        acc.z += v0.z * w0; acc.w += v0.w * w0;
    }

    float* agg = buf_ptr(agg_sel);
    *(float4*)&agg[i * 64 + c4] =
        make_float4(acc.x * dv, acc.y * dv, acc.z * dv, acc.w * dv);
}

// ---------------- heads: demand / inventory (one warp per node) ----------------
__global__ void __launch_bounds__(256) heads_k(
    int in_sel, const float* __restrict__ cb,
    const float* __restrict__ Wd1, const float* __restrict__ bd1,
    const float* __restrict__ Wd2, const float* __restrict__ bd2,
    const float* __restrict__ Wi1, const float* __restrict__ bi1,
    const float* __restrict__ Wi2, const float* __restrict__ bi2,
    float* __restrict__ out, int N)
{
    __shared__ float sWd1[64 * 32];
    __shared__ float sWi1[64 * 32];
    __shared__ float sWd2[32], sWi2[32], sbd1[32], sbi1[32], scb[64];
    __shared__ float sh[8 * 64];

    int t = threadIdx.x;
    {
        const float4* wd = (const float4*)Wd1;
        const float4* wi = (const float4*)Wi1;
        float4* swd = (float4*)sWd1;
        float4* swi = (float4*)sWi1;
        swd[t] = wd[t]; swd[t + 256] = wd[t + 256];
        swi[t] = wi[t]; swi[t + 256] = wi[t + 256];
    }
    if (t < 32) { sWd2[t] = Wd2[t]; sWi2[t] = Wi2[t]; sbd1[t] = bd1[t]; sbi1[t] = bi1[t]; }
    if (t < 64) scb[t] = cb[t];
    __syncthreads();

    const float* in = buf_ptr(in_sel);
    int w = t >> 5, lane = t & 31;
    int i = blockIdx.x * 8 + w;

    if (i < N) {
        float v0 = fmaxf(in[i * 64 + lane]      + scb[lane],      0.f);
        float v1 = fmaxf(in[i * 64 + lane + 32] + scb[lane + 32], 0.f);
        sh[w * 64 + lane] = v0;
        sh[w * 64 + lane + 32] = v1;
    }
    __syncwarp();
    if (i >= N) return;

    float ad = sbd1[lane];
    float ai = sbi1[lane];
#pragma unroll 16
    for (int k = 0; k < 64; k++) {
        float hv = sh[w * 64 + k];
        ad += hv * sWd1[k * 32 + lane];
        ai += hv * sWi1[k * 32 + lane];
    }
    float vd = fmaxf(ad, 0.f) * sWd2[lane];
    float vi = fmaxf(ai, 0.f) * sWi2[lane];
#pragma unroll
    for (int o = 16; o > 0; o >>= 1) {
        vd += __shfl_xor_sync(0xffffffffu, vd, o);
        vi += __shfl_xor_sync(0xffffffffu, vi, o);
    }
    if (lane == 0) {
        out[i]     = vd + bd2[0];
        out[N + i] = vi + bi2[0];
    }
}

// ---------------- launch ----------------
extern "C" void kernel_launch(void* const* d_in, const int* in_sizes, int n_in,
                              void* d_out, int out_size)
{
    const float* x      = (const float*)d_in[0];
    const int*   ei     = (const int*)d_in[1];     // int32 (JAX x64 off)
    const float* W_enc  = (const float*)d_in[2];
    const float* b_enc  = (const float*)d_in[3];
    const float* conv_W = (const float*)d_in[4];   // [3][64][64]
    const float* conv_b = (const float*)d_in[5];   // [3][64]
    const float* W_d1   = (const float*)d_in[6];
    const float* b_d1   = (const float*)d_in[7];
    const float* W_d2   = (const float*)d_in[8];
    const float* b_d2   = (const float*)d_in[9];
    const float* W_i1   = (const float*)d_in[10];
    const float* b_i1   = (const float*)d_in[11];
    const float* W_i2   = (const float*)d_in[12];
    const float* b_i2   = (const float*)d_in[13];
    float* out = (float*)d_out;

    int N = in_sizes[0] / 5;
    int E = in_sizes[1] / 2;
    const int* src = ei;       // edge_index[0] (source)
    const int* dst = ei + E;   // edge_index[1] (target)

    int nbE = (E + 255) / 256;
    int gemmB = (N + 63) / 64;
    int aggB  = (N * 16 + 255) / 256;

    // 0: encoder (+ g_cnt clear)
    encoder_k<<<(N * 16 + 255) / 256, 256>>>(x, W_enc, b_enc, N);
    // 1: degree histogram
    deg_count_k<<<nbE, 256>>>(dst, E);
    // 2: scan + dinv + cursors
    scan_dinv_k<<<1, 1024>>>(N);
    // 3: layer0 gemm  (ncu captures my launch index 3)
    gemm_k<<<gemmB, 128>>>(0, conv_W + 0 * 4096, nullptr, 0, N);
    // 4: CSR fill
    csr_fill_k<<<nbE, 256>>>(src, dst, E);
    // 5: layer0 aggregate
    aggregate_k<<<aggB, 256>>>(1, N);
    // 6-7: layer1
    gemm_k<<<gemmB, 128>>>(1, conv_W + 1 * 4096, conv_b + 0 * 64, 1, N);
    aggregate_k<<<aggB, 256>>>(2, N);
    // 8-9: layer2
    gemm_k<<<gemmB, 128>>>(2, conv_W + 2 * 4096, conv_b + 1 * 64, 1, N);
    aggregate_k<<<aggB, 256>>>(1, N);
    // 10: heads
    heads_k<<<(N + 7) / 8, 256>>>(1, conv_b + 2 * 64,
                                  W_d1, b_d1, W_d2, b_d2,
                                  W_i1, b_i1, W_i2, b_i2,
                                  out, N);
}